// round 15
// baseline (speedup 1.0000x reference)
#include <cuda_runtime.h>
#include <cuda_bf16.h>
#include <math.h>
#include <stdint.h>

#define NQ   2048
#define NW   64
#define CCH  640
#define NITER 100

typedef unsigned long long u64;
typedef unsigned int u32;

// ---------------- helpers ----------------
__device__ __forceinline__ u64 pack2(float lo, float hi) {
    u64 r; asm("mov.b64 %0, {%1,%2};" : "=l"(r) : "f"(lo), "f"(hi)); return r;
}
__device__ __forceinline__ void unpack2(u64 v, float& lo, float& hi) {
    asm("mov.b64 {%0,%1}, %2;" : "=f"(lo), "=f"(hi) : "l"(v));
}
__device__ __forceinline__ void ffma2(u64& d, u64 a, u64 b) {
    asm("fma.rn.f32x2 %0, %1, %2, %0;" : "+l"(d) : "l"(a), "l"(b));
}
// m16n8k16 bf16 MMA (fp32 accum)
__device__ __forceinline__ void mma_bf16(float4& d, u32 a0,u32 a1,u32 a2,u32 a3, u32 b0,u32 b1) {
    asm("mma.sync.aligned.m16n8k16.row.col.f32.bf16.bf16.f32 "
        "{%0,%1,%2,%3},{%4,%5,%6,%7},{%8,%9},{%0,%1,%2,%3};"
        : "+f"(d.x),"+f"(d.y),"+f"(d.z),"+f"(d.w)
        : "r"(a0),"r"(a1),"r"(a2),"r"(a3),"r"(b0),"r"(b1));
}
__device__ __forceinline__ void cp16(u32 saddr, const void* gptr) {
    asm volatile("cp.async.cg.shared.global [%0], [%1], 16;" :: "r"(saddr), "l"(gptr));
}
#define CP_COMMIT() asm volatile("cp.async.commit_group;" ::: "memory")
#define CP_WAIT0()  asm volatile("cp.async.wait_group 0;"  ::: "memory")

// ---------------- scratch ----------------
__device__ __nv_bfloat16 g_qnA_hi[(size_t)(NQ*5)*CCH];  // normalized query feats, [row][k]
__device__ __nv_bfloat16 g_qnA_lo[(size_t)(NQ*5)*CCH];
__device__ __nv_bfloat16 g_pnB_hi[(size_t)(NW*5)*CCH];  // normalized proto feats, [n][k]
__device__ __nv_bfloat16 g_pnB_lo[(size_t)(NW*5)*CCH];
__device__ float g_qfA[(NQ*5)*CCH];     // raw query features, row (m*5+p), col c
__device__ float g_pfB[5*CCH*NW];       // raw proto features [p][c][w]
__device__ float g_sim[(size_t)NQ*NW*25];
__device__ float g_comb[(size_t)NQ*NW*5];

// ---------------- Kernel 1: patch-pool features (cp.async per-warp staging) ----------------
__global__ void __launch_bounds__(640, 3) feat_kernel(const float* __restrict__ proto,
                                                      const float* __restrict__ query) {
    extern __shared__ float simg[];
    int b = blockIdx.x;               // 0..2047 query, 2048..2111 proto
    int c = threadIdx.x;
    int lane = c & 31, wid = c >> 5;

    const float* base = (b < NQ) ? (query + (size_t)b*CCH*25)
                                 : (proto + (size_t)(b-NQ)*CCH*25);
    // warp stages its 800 floats gmem->smem via cp.async.cg (bypasses L1/RF)
    {
        u32 dst = (u32)__cvta_generic_to_shared(simg + wid*800);
        const float* src = base + wid*800;
#pragma unroll
        for (int i = lane; i < 200; i += 32) cp16(dst + i*16u, src + i*4);
        CP_COMMIT();
        CP_WAIT0();
        __syncwarp();
    }

    float v[25];
    const float* mych = simg + wid*800 + lane*25;
#pragma unroll
    for (int k = 0; k < 25; ++k) v[k] = mych[k];

    float s02[5], s24[5], s14[5];
#pragma unroll
    for (int col = 0; col < 5; ++col) {
        s02[col] = v[col]    + v[5+col]  + v[10+col];
        s24[col] = v[10+col] + v[15+col] + v[20+col];
        s14[col] = v[5+col] + v[10+col] + v[15+col] + v[20+col];
    }
    float fea[5];
    fea[0] = (s02[0]+s02[1]+s02[2]) * (1.f/9.f);
    fea[1] = (s24[0]+s24[1]+s24[2]) * (1.f/9.f);
    fea[2] = (s14[1]+s14[2]+s14[3]+s14[4]) * (1.f/16.f);
    fea[3] = (s02[2]+s02[3]+s02[4]) * (1.f/9.f);
    fea[4] = (s24[2]+s24[3]+s24[4]) * (1.f/9.f);

    if (b < NQ) {
#pragma unroll
        for (int p = 0; p < 5; ++p) g_qfA[(size_t)(b*5+p)*CCH + c] = fea[p];
    } else {
        int w = b - NQ;
#pragma unroll
        for (int p = 0; p < 5; ++p) g_pfB[((size_t)p*CCH + c)*NW + w] = fea[p];
    }

    __shared__ float sred[5][20];
    __shared__ float sstat[5];

    float r[5];
#pragma unroll
    for (int p = 0; p < 5; ++p) r[p] = fea[p];
#pragma unroll
    for (int o = 16; o; o >>= 1)
#pragma unroll
        for (int p = 0; p < 5; ++p) r[p] += __shfl_down_sync(0xffffffffu, r[p], o);
    if (lane == 0)
#pragma unroll
        for (int p = 0; p < 5; ++p) sred[p][wid] = r[p];
    __syncthreads();
    if (c < 5) {
        float s = 0.f;
        for (int q = 0; q < 20; ++q) s += sred[c][q];
        sstat[c] = s * (1.f/640.f);
    }
    __syncthreads();
    float cent[5];
#pragma unroll
    for (int p = 0; p < 5; ++p) cent[p] = fea[p] - sstat[p];

#pragma unroll
    for (int p = 0; p < 5; ++p) r[p] = cent[p]*cent[p];
#pragma unroll
    for (int o = 16; o; o >>= 1)
#pragma unroll
        for (int p = 0; p < 5; ++p) r[p] += __shfl_down_sync(0xffffffffu, r[p], o);
    __syncthreads();
    if (lane == 0)
#pragma unroll
        for (int p = 0; p < 5; ++p) sred[p][wid] = r[p];
    __syncthreads();
    if (c < 5) {
        float s = 0.f;
        for (int q = 0; q < 20; ++q) s += sred[c][q];
        sstat[c] = 1.f / fmaxf(sqrtf(s), 1e-8f);
    }
    __syncthreads();

    if (b < NQ) {
#pragma unroll
        for (int i = 0; i < 5; ++i) {
            float q = cent[i]*sstat[i];
            __nv_bfloat16 h = __float2bfloat16(q);
            float hf = __bfloat162float(h);
            size_t idx = (size_t)(b*5+i)*CCH + c;
            g_qnA_hi[idx] = h;
            g_qnA_lo[idx] = __float2bfloat16(q - hf);
        }
    } else {
        int w = b - NQ;
#pragma unroll
        for (int j = 0; j < 5; ++j) {
            float q = cent[j]*sstat[j];
            __nv_bfloat16 h = __float2bfloat16(q);
            float hf = __bfloat162float(h);
            size_t idx = (size_t)(w*5+j)*CCH + c;   // B row-major [n][k]
            g_pnB_hi[idx] = h;
            g_pnB_lo[idx] = __float2bfloat16(q - hf);
        }
    }
}

// ---------------- Kernel 2: mega GEMM, 128-thread blocks, 6 blocks/SM ----------------
// bx<5: sim bf16x3, M=64 x N=64 tiles (4 warps); bx==5: comb FFMA2, 64-row tiles
#define TBM 64
#define TBN 64
#define TBK 32
#define LDA 40            // bf16 elems per smem row (80B)
// bf16-elem offsets: As_hi 0 | As_lo 2560 | Bs_hi 5120 | Bs_lo 7680 | end 10240
#define OFF_AL 2560
#define OFF_BH 5120
#define OFF_BL 7680
#define SMEM_GEMM (10240*2)   // 20480 B (comb branch uses 8192 B)

__global__ void __launch_bounds__(128, 6) gemm_mega() {
    extern __shared__ float sm[];
    int tid = threadIdx.x;
    int bx = blockIdx.x, by = blockIdx.y;

    if (bx < 5) {
        __nv_bfloat16* smb = (__nv_bfloat16*)sm;
        int lane = tid & 31;
        int w = tid >> 5;          // 4 warps
        int warpM = w & 1;         // 0..1 -> 32 rows each
        int warpN = w >> 1;        // 0..1 -> 32 cols each
        int grp = lane >> 2;       // 0..7
        int tig = lane & 3;        // 0..3

        float4 acc[2][4];
#pragma unroll
        for (int mt = 0; mt < 2; ++mt)
#pragma unroll
            for (int nt = 0; nt < 4; ++nt) acc[mt][nt] = make_float4(0.f,0.f,0.f,0.f);

        const __nv_bfloat16* Ah = g_qnA_hi + (size_t)(by*TBM)*CCH;
        const __nv_bfloat16* Al = g_qnA_lo + (size_t)(by*TBM)*CCH;
        const __nv_bfloat16* Bh = g_pnB_hi + (size_t)(bx*TBN)*CCH;
        const __nv_bfloat16* Bl = g_pnB_lo + (size_t)(bx*TBN)*CCH;

        int r32 = tid >> 2, c4 = tid & 3;   // rows r32, r32+32 ; col group c4

        for (int k0 = 0; k0 < CCH; k0 += TBK) {
            float4 ah[2], al[2], bh[2], bl[2];
#pragma unroll
            for (int q = 0; q < 2; ++q) {
                int row = r32 + 32*q;
                ah[q] = *(const float4*)(Ah + (size_t)row*CCH + k0 + c4*8);
                al[q] = *(const float4*)(Al + (size_t)row*CCH + k0 + c4*8);
                bh[q] = *(const float4*)(Bh + (size_t)row*CCH + k0 + c4*8);
                bl[q] = *(const float4*)(Bl + (size_t)row*CCH + k0 + c4*8);
            }
            __syncthreads();
#pragma unroll
            for (int q = 0; q < 2; ++q) {
                int row = r32 + 32*q;
                *(float4*)(smb + row*LDA + c4*8)          = ah[q];
                *(float4*)(smb + OFF_AL + row*LDA + c4*8) = al[q];
                *(float4*)(smb + OFF_BH + row*LDA + c4*8) = bh[q];
                *(float4*)(smb + OFF_BL + row*LDA + c4*8) = bl[q];
            }
            __syncthreads();

#pragma unroll
            for (int kk = 0; kk < TBK; kk += 16) {
                u32 ahi[2][4], alo[2][4];
#pragma unroll
                for (int mt = 0; mt < 2; ++mt) {
                    int r0 = warpM*32 + mt*16;
                    const __nv_bfloat16* pa = smb + (r0+grp)*LDA + kk + 2*tig;
                    const __nv_bfloat16* pb = smb + (r0+grp+8)*LDA + kk + 2*tig;
                    ahi[mt][0] = *(const u32*)(pa);
                    ahi[mt][1] = *(const u32*)(pb);
                    ahi[mt][2] = *(const u32*)(pa + 8);
                    ahi[mt][3] = *(const u32*)(pb + 8);
                    alo[mt][0] = *(const u32*)(pa + OFF_AL);
                    alo[mt][1] = *(const u32*)(pb + OFF_AL);
                    alo[mt][2] = *(const u32*)(pa + OFF_AL + 8);
                    alo[mt][3] = *(const u32*)(pb + OFF_AL + 8);
                }
                u32 bhi[4][2], blo[4][2];
#pragma unroll
                for (int nt = 0; nt < 4; ++nt) {
                    int n0 = warpN*32 + nt*8 + grp;
                    const __nv_bfloat16* pb = smb + OFF_BH + n0*LDA + kk + 2*tig;
                    bhi[nt][0] = *(const u32*)(pb);
                    bhi[nt][1] = *(const u32*)(pb + 8);
                    blo[nt][0] = *(const u32*)(pb + (OFF_BL - OFF_BH));
                    blo[nt][1] = *(const u32*)(pb + (OFF_BL - OFF_BH) + 8);
                }
#pragma unroll
                for (int mt = 0; mt < 2; ++mt)
#pragma unroll
                    for (int nt = 0; nt < 4; ++nt) {
                        mma_bf16(acc[mt][nt], ahi[mt][0],ahi[mt][1],ahi[mt][2],ahi[mt][3],
                                 bhi[nt][0],bhi[nt][1]);
                        mma_bf16(acc[mt][nt], ahi[mt][0],ahi[mt][1],ahi[mt][2],ahi[mt][3],
                                 blo[nt][0],blo[nt][1]);
                        mma_bf16(acc[mt][nt], alo[mt][0],alo[mt][1],alo[mt][2],alo[mt][3],
                                 bhi[nt][0],bhi[nt][1]);
                    }
            }
            __syncthreads();
        }

        // epilogue: C(row,col) -> g_sim[(m*64+w)*25 + i*5 + j]
#pragma unroll
        for (int mt = 0; mt < 2; ++mt) {
#pragma unroll
            for (int nt = 0; nt < 4; ++nt) {
                int row0 = by*TBM + warpM*32 + mt*16 + grp;
                int col0 = bx*TBN + warpN*32 + nt*8 + 2*tig;
                float vals[4] = {acc[mt][nt].x, acc[mt][nt].y, acc[mt][nt].z, acc[mt][nt].w};
#pragma unroll
                for (int e = 0; e < 4; ++e) {
                    int row = row0 + (e >> 1)*8;
                    int col = col0 + (e & 1);
                    int m = row/5, ii = row%5, ww = col/5, jj = col%5;
                    g_sim[((size_t)(m*NW + ww))*25 + ii*5 + jj] = vals[e];
                }
            }
        }
    } else {
        // ---------- comb GEMM: per-p (2048x64) = qfA_p * pfB_p, 64-row tiles, FFMA2 ----------
        int tile = by & 31;       // 0..31 -> 64 rows each
        int p    = by >> 5;       // 0..4
        float* As = sm;           // [16][64]
        float* Bs = sm + 16*64;   // [16][64]

        const float* A = g_qfA + p*CCH;            const int lda = 5*CCH;
        const float* B = g_pfB + (size_t)p*CCH*NW; const int ldb = NW;

        int arow = tid >> 2;           // 0..31 (rows arow, arow+32)
        int acol = (tid & 3) * 4;
        int brow = tid >> 4;           // 0..7 (rows brow, brow+8)
        int bcol = (tid & 15) * 4;
        int ty = tid >> 4, tx = tid & 15;

        u64 acc[4][4];
#pragma unroll
        for (int i = 0; i < 4; ++i)
#pragma unroll
            for (int j = 0; j < 4; ++j) acc[i][j] = 0ull;

        const float* Ab = A + (size_t)(tile*64)*lda;

        for (int k0 = 0; k0 < CCH; k0 += 16) {
            float4 a0 = *(const float4*)(Ab + (size_t)arow*lda + k0 + acol);
            float4 a1 = *(const float4*)(Ab + (size_t)(arow+32)*lda + k0 + acol);
            float4 b0 = *(const float4*)(B  + (size_t)(k0+brow)*ldb + bcol);
            float4 b1 = *(const float4*)(B  + (size_t)(k0+brow+8)*ldb + bcol);
            __syncthreads();
            As[(acol+0)*64 + arow]    = a0.x; As[(acol+1)*64 + arow]    = a0.y;
            As[(acol+2)*64 + arow]    = a0.z; As[(acol+3)*64 + arow]    = a0.w;
            As[(acol+0)*64 + arow+32] = a1.x; As[(acol+1)*64 + arow+32] = a1.y;
            As[(acol+2)*64 + arow+32] = a1.z; As[(acol+3)*64 + arow+32] = a1.w;
            *(float4*)&Bs[brow*64 + bcol]     = b0;
            *(float4*)&Bs[(brow+8)*64 + bcol] = b1;
            __syncthreads();
#pragma unroll
            for (int k = 0; k < 16; ++k) {
                const u64* ap = (const u64*)&As[k*64 + ty*8];
                u64 a2[4] = {ap[0], ap[1], ap[2], ap[3]};
                float4 bv = *(const float4*)&Bs[k*64 + tx*4];
                u64 b2[4] = {pack2(bv.x,bv.x), pack2(bv.y,bv.y),
                             pack2(bv.z,bv.z), pack2(bv.w,bv.w)};
#pragma unroll
                for (int ip = 0; ip < 4; ++ip)
#pragma unroll
                    for (int j = 0; j < 4; ++j) ffma2(acc[ip][j], a2[ip], b2[j]);
            }
        }

        int row0 = tile*64 + ty*8;
        int col0 = tx*4;
#pragma unroll
        for (int ip = 0; ip < 4; ++ip)
#pragma unroll
            for (int j = 0; j < 4; ++j) {
                float lo, hi; unpack2(acc[ip][j], lo, hi);
                int r_lo = row0 + 2*ip, r_hi = r_lo + 1;
                int cc = col0 + j;
                g_comb[(size_t)r_lo*(NW*5) + cc*5 + p] = lo;
                g_comb[(size_t)r_hi*(NW*5) + cc*5 + p] = hi;
            }
    }
}

// ---------------- Kernel 3: Sinkhorn (scalar, rescaled) + early-exit (5-iter chunks) ----------------
__global__ void __launch_bounds__(256) sinkhorn_kernel(float* __restrict__ out) {
    int t = blockIdx.x*256 + threadIdx.x;

    float a[5]; float ws = 0.f;
#pragma unroll
    for (int p = 0; p < 5; ++p) {
        float wv = fmaxf(g_comb[(size_t)t*5 + p], 0.f) + 0.00101f;
        a[p] = wv; ws += wv;
    }
    float sc = __fdividef(5.f, ws);
#pragma unroll
    for (int p = 0; p < 5; ++p) a[p] *= sc;

    float K[25];
    const float* sp = g_sim + (size_t)t*25;
#pragma unroll
    for (int e = 0; e < 25; ++e) K[e] = __expf(20.f * sp[e]);

    float u[5], v[5];
#pragma unroll
    for (int j = 0; j < 5; ++j) v[j] = 1.f;

#pragma unroll 1
    for (int chunk = 0; chunk < 20; ++chunk) {
        float vs[5];
#pragma unroll
        for (int j = 0; j < 5; ++j) vs[j] = v[j];

#pragma unroll
        for (int s = 0; s < 5; ++s) {
#pragma unroll
            for (int i = 0; i < 5; ++i) {
                float acc = K[i*5+0]*v[0];
                acc = fmaf(K[i*5+1], v[1], acc);
                acc = fmaf(K[i*5+2], v[2], acc);
                acc = fmaf(K[i*5+3], v[3], acc);
                acc = fmaf(K[i*5+4], v[4], acc);
                u[i] = __fdividef(a[i], acc);
            }
#pragma unroll
            for (int j = 0; j < 5; ++j) {
                float acc = K[0*5+j]*u[0];
                acc = fmaf(K[1*5+j], u[1], acc);
                acc = fmaf(K[2*5+j], u[2], acc);
                acc = fmaf(K[3*5+j], u[3], acc);
                acc = fmaf(K[4*5+j], u[4], acc);
                v[j] = __fdividef(a[j], acc);
            }
        }

        bool conv = true;
#pragma unroll
        for (int j = 0; j < 5; ++j)
            conv = conv && (fabsf(v[j] - vs[j]) <= 1e-6f * v[j]);
        if (__all_sync(0xffffffffu, conv)) break;
    }

    float L = 0.f;
#pragma unroll
    for (int i = 0; i < 5; ++i) {
        float ui = u[i];
#pragma unroll
        for (int j = 0; j < 5; ++j)
            L = fmaf(sp[i*5+j] * ui, K[i*5+j]*v[j], L);
    }
    out[t] = L * 2.5f;
}

// ---------------- launch ----------------
extern "C" void kernel_launch(void* const* d_in, const int* in_sizes, int n_in,
                              void* d_out, int out_size) {
    const float* proto = (const float*)d_in[0];
    const float* query = (const float*)d_in[1];
    if (n_in >= 2 && in_sizes[0] > in_sizes[1]) {
        proto = (const float*)d_in[1];
        query = (const float*)d_in[0];
    }
    float* out = (float*)d_out;

    static bool attr_set = false;
    if (!attr_set) {
        cudaFuncSetAttribute(feat_kernel, cudaFuncAttributeMaxDynamicSharedMemorySize, 64000);
        cudaFuncSetAttribute(gemm_mega, cudaFuncAttributeMaxDynamicSharedMemorySize, SMEM_GEMM);
        attr_set = true;
    }

    feat_kernel<<<NQ + NW, 640, 64000>>>(proto, query);
    gemm_mega<<<dim3(6, 160), 128, SMEM_GEMM>>>();  // bx<5: sim (M=64); bx==5: comb (by=tile+32p)
    sinkhorn_kernel<<<(NQ*NW)/256, 256>>>(out);
}

// round 16
// speedup vs baseline: 1.0389x; 1.0389x over previous
#include <cuda_runtime.h>
#include <cuda_bf16.h>
#include <math.h>
#include <stdint.h>

#define NQ   2048
#define NW   64
#define CCH  640
#define NITER 100

typedef unsigned long long u64;
typedef unsigned int u32;

// ---------------- helpers ----------------
__device__ __forceinline__ u64 pack2(float lo, float hi) {
    u64 r; asm("mov.b64 %0, {%1,%2};" : "=l"(r) : "f"(lo), "f"(hi)); return r;
}
__device__ __forceinline__ void unpack2(u64 v, float& lo, float& hi) {
    asm("mov.b64 {%0,%1}, %2;" : "=f"(lo), "=f"(hi) : "l"(v));
}
__device__ __forceinline__ void ffma2(u64& d, u64 a, u64 b) {
    asm("fma.rn.f32x2 %0, %1, %2, %0;" : "+l"(d) : "l"(a), "l"(b));
}
// m16n8k16 bf16 MMA (fp32 accum)
__device__ __forceinline__ void mma_bf16(float4& d, u32 a0,u32 a1,u32 a2,u32 a3, u32 b0,u32 b1) {
    asm("mma.sync.aligned.m16n8k16.row.col.f32.bf16.bf16.f32 "
        "{%0,%1,%2,%3},{%4,%5,%6,%7},{%8,%9},{%0,%1,%2,%3};"
        : "+f"(d.x),"+f"(d.y),"+f"(d.z),"+f"(d.w)
        : "r"(a0),"r"(a1),"r"(a2),"r"(a3),"r"(b0),"r"(b1));
}
__device__ __forceinline__ void cp16(u32 saddr, const void* gptr) {
    asm volatile("cp.async.cg.shared.global [%0], [%1], 16;" :: "r"(saddr), "l"(gptr));
}
#define CP_COMMIT() asm volatile("cp.async.commit_group;" ::: "memory")
#define CP_WAIT0()  asm volatile("cp.async.wait_group 0;"  ::: "memory")

// ---------------- scratch ----------------
__device__ __nv_bfloat16 g_qnA_hi[(size_t)(NQ*5)*CCH];  // normalized query feats, [row][k]
__device__ __nv_bfloat16 g_qnA_lo[(size_t)(NQ*5)*CCH];
__device__ __nv_bfloat16 g_pnB_hi[(size_t)(NW*5)*CCH];  // normalized proto feats, [n][k]
__device__ __nv_bfloat16 g_pnB_lo[(size_t)(NW*5)*CCH];
__device__ float g_qfA[(NQ*5)*CCH];     // raw query features, row (m*5+p), col c
__device__ float g_pfB[5*CCH*NW];       // raw proto features [p][c][w]
__device__ float g_sim[(size_t)NQ*NW*25];
__device__ float g_comb[(size_t)NQ*NW*5];

// ---------------- Kernel 1: patch-pool features (cp.async per-warp staging) ----------------
__global__ void __launch_bounds__(640, 3) feat_kernel(const float* __restrict__ proto,
                                                      const float* __restrict__ query) {
    extern __shared__ float simg[];
    int b = blockIdx.x;               // 0..2047 query, 2048..2111 proto
    int c = threadIdx.x;
    int lane = c & 31, wid = c >> 5;

    const float* base = (b < NQ) ? (query + (size_t)b*CCH*25)
                                 : (proto + (size_t)(b-NQ)*CCH*25);
    // warp stages its 800 floats gmem->smem via cp.async.cg (bypasses L1/RF)
    {
        u32 dst = (u32)__cvta_generic_to_shared(simg + wid*800);
        const float* src = base + wid*800;
#pragma unroll
        for (int i = lane; i < 200; i += 32) cp16(dst + i*16u, src + i*4);
        CP_COMMIT();
        CP_WAIT0();
        __syncwarp();
    }

    float v[25];
    const float* mych = simg + wid*800 + lane*25;
#pragma unroll
    for (int k = 0; k < 25; ++k) v[k] = mych[k];

    float s02[5], s24[5], s14[5];
#pragma unroll
    for (int col = 0; col < 5; ++col) {
        s02[col] = v[col]    + v[5+col]  + v[10+col];
        s24[col] = v[10+col] + v[15+col] + v[20+col];
        s14[col] = v[5+col] + v[10+col] + v[15+col] + v[20+col];
    }
    float fea[5];
    fea[0] = (s02[0]+s02[1]+s02[2]) * (1.f/9.f);
    fea[1] = (s24[0]+s24[1]+s24[2]) * (1.f/9.f);
    fea[2] = (s14[1]+s14[2]+s14[3]+s14[4]) * (1.f/16.f);
    fea[3] = (s02[2]+s02[3]+s02[4]) * (1.f/9.f);
    fea[4] = (s24[2]+s24[3]+s24[4]) * (1.f/9.f);

    if (b < NQ) {
#pragma unroll
        for (int p = 0; p < 5; ++p) g_qfA[(size_t)(b*5+p)*CCH + c] = fea[p];
    } else {
        int w = b - NQ;
#pragma unroll
        for (int p = 0; p < 5; ++p) g_pfB[((size_t)p*CCH + c)*NW + w] = fea[p];
    }

    __shared__ float sred[5][20];
    __shared__ float sstat[5];

    float r[5];
#pragma unroll
    for (int p = 0; p < 5; ++p) r[p] = fea[p];
#pragma unroll
    for (int o = 16; o; o >>= 1)
#pragma unroll
        for (int p = 0; p < 5; ++p) r[p] += __shfl_down_sync(0xffffffffu, r[p], o);
    if (lane == 0)
#pragma unroll
        for (int p = 0; p < 5; ++p) sred[p][wid] = r[p];
    __syncthreads();
    if (c < 5) {
        float s = 0.f;
        for (int q = 0; q < 20; ++q) s += sred[c][q];
        sstat[c] = s * (1.f/640.f);
    }
    __syncthreads();
    float cent[5];
#pragma unroll
    for (int p = 0; p < 5; ++p) cent[p] = fea[p] - sstat[p];

#pragma unroll
    for (int p = 0; p < 5; ++p) r[p] = cent[p]*cent[p];
#pragma unroll
    for (int o = 16; o; o >>= 1)
#pragma unroll
        for (int p = 0; p < 5; ++p) r[p] += __shfl_down_sync(0xffffffffu, r[p], o);
    __syncthreads();
    if (lane == 0)
#pragma unroll
        for (int p = 0; p < 5; ++p) sred[p][wid] = r[p];
    __syncthreads();
    if (c < 5) {
        float s = 0.f;
        for (int q = 0; q < 20; ++q) s += sred[c][q];
        sstat[c] = 1.f / fmaxf(sqrtf(s), 1e-8f);
    }
    __syncthreads();

    if (b < NQ) {
#pragma unroll
        for (int i = 0; i < 5; ++i) {
            float q = cent[i]*sstat[i];
            __nv_bfloat16 h = __float2bfloat16(q);
            float hf = __bfloat162float(h);
            size_t idx = (size_t)(b*5+i)*CCH + c;
            g_qnA_hi[idx] = h;
            g_qnA_lo[idx] = __float2bfloat16(q - hf);
        }
    } else {
        int w = b - NQ;
#pragma unroll
        for (int j = 0; j < 5; ++j) {
            float q = cent[j]*sstat[j];
            __nv_bfloat16 h = __float2bfloat16(q);
            float hf = __bfloat162float(h);
            size_t idx = (size_t)(w*5+j)*CCH + c;   // B row-major [n][k]
            g_pnB_hi[idx] = h;
            g_pnB_lo[idx] = __float2bfloat16(q - hf);
        }
    }
}

// ---------------- Kernel 2: mega GEMM, 128-thread blocks, 5 blocks/SM (R14 winner) ----------
// bx<5: sim bf16x3, M=64 x N=64 tiles (4 warps); bx==5: comb FFMA2, 64-row tiles
#define TBM 64
#define TBN 64
#define TBK 32
#define LDA 40            // bf16 elems per smem row (80B)
// bf16-elem offsets: As_hi 0 | As_lo 2560 | Bs_hi 5120 | Bs_lo 7680 | end 10240
#define OFF_AL 2560
#define OFF_BH 5120
#define OFF_BL 7680
#define SMEM_GEMM (10240*2)   // 20480 B (comb branch uses 8192 B)

__global__ void __launch_bounds__(128, 5) gemm_mega() {
    extern __shared__ float sm[];
    int tid = threadIdx.x;
    int bx = blockIdx.x, by = blockIdx.y;

    if (bx < 5) {
        __nv_bfloat16* smb = (__nv_bfloat16*)sm;
        int lane = tid & 31;
        int w = tid >> 5;          // 4 warps
        int warpM = w & 1;         // 0..1 -> 32 rows each
        int warpN = w >> 1;        // 0..1 -> 32 cols each
        int grp = lane >> 2;       // 0..7
        int tig = lane & 3;        // 0..3

        float4 acc[2][4];
#pragma unroll
        for (int mt = 0; mt < 2; ++mt)
#pragma unroll
            for (int nt = 0; nt < 4; ++nt) acc[mt][nt] = make_float4(0.f,0.f,0.f,0.f);

        const __nv_bfloat16* Ah = g_qnA_hi + (size_t)(by*TBM)*CCH;
        const __nv_bfloat16* Al = g_qnA_lo + (size_t)(by*TBM)*CCH;
        const __nv_bfloat16* Bh = g_pnB_hi + (size_t)(bx*TBN)*CCH;
        const __nv_bfloat16* Bl = g_pnB_lo + (size_t)(bx*TBN)*CCH;

        int r32 = tid >> 2, c4 = tid & 3;   // rows r32, r32+32 ; col group c4

        for (int k0 = 0; k0 < CCH; k0 += TBK) {
            float4 ah[2], al[2], bh[2], bl[2];
#pragma unroll
            for (int q = 0; q < 2; ++q) {
                int row = r32 + 32*q;
                ah[q] = *(const float4*)(Ah + (size_t)row*CCH + k0 + c4*8);
                al[q] = *(const float4*)(Al + (size_t)row*CCH + k0 + c4*8);
                bh[q] = *(const float4*)(Bh + (size_t)row*CCH + k0 + c4*8);
                bl[q] = *(const float4*)(Bl + (size_t)row*CCH + k0 + c4*8);
            }
            __syncthreads();
#pragma unroll
            for (int q = 0; q < 2; ++q) {
                int row = r32 + 32*q;
                *(float4*)(smb + row*LDA + c4*8)          = ah[q];
                *(float4*)(smb + OFF_AL + row*LDA + c4*8) = al[q];
                *(float4*)(smb + OFF_BH + row*LDA + c4*8) = bh[q];
                *(float4*)(smb + OFF_BL + row*LDA + c4*8) = bl[q];
            }
            __syncthreads();

#pragma unroll
            for (int kk = 0; kk < TBK; kk += 16) {
                u32 ahi[2][4], alo[2][4];
#pragma unroll
                for (int mt = 0; mt < 2; ++mt) {
                    int r0 = warpM*32 + mt*16;
                    const __nv_bfloat16* pa = smb + (r0+grp)*LDA + kk + 2*tig;
                    const __nv_bfloat16* pb = smb + (r0+grp+8)*LDA + kk + 2*tig;
                    ahi[mt][0] = *(const u32*)(pa);
                    ahi[mt][1] = *(const u32*)(pb);
                    ahi[mt][2] = *(const u32*)(pa + 8);
                    ahi[mt][3] = *(const u32*)(pb + 8);
                    alo[mt][0] = *(const u32*)(pa + OFF_AL);
                    alo[mt][1] = *(const u32*)(pb + OFF_AL);
                    alo[mt][2] = *(const u32*)(pa + OFF_AL + 8);
                    alo[mt][3] = *(const u32*)(pb + OFF_AL + 8);
                }
                u32 bhi[4][2], blo[4][2];
#pragma unroll
                for (int nt = 0; nt < 4; ++nt) {
                    int n0 = warpN*32 + nt*8 + grp;
                    const __nv_bfloat16* pb = smb + OFF_BH + n0*LDA + kk + 2*tig;
                    bhi[nt][0] = *(const u32*)(pb);
                    bhi[nt][1] = *(const u32*)(pb + 8);
                    blo[nt][0] = *(const u32*)(pb + (OFF_BL - OFF_BH));
                    blo[nt][1] = *(const u32*)(pb + (OFF_BL - OFF_BH) + 8);
                }
#pragma unroll
                for (int mt = 0; mt < 2; ++mt)
#pragma unroll
                    for (int nt = 0; nt < 4; ++nt) {
                        mma_bf16(acc[mt][nt], ahi[mt][0],ahi[mt][1],ahi[mt][2],ahi[mt][3],
                                 bhi[nt][0],bhi[nt][1]);
                        mma_bf16(acc[mt][nt], ahi[mt][0],ahi[mt][1],ahi[mt][2],ahi[mt][3],
                                 blo[nt][0],blo[nt][1]);
                        mma_bf16(acc[mt][nt], alo[mt][0],alo[mt][1],alo[mt][2],alo[mt][3],
                                 bhi[nt][0],bhi[nt][1]);
                    }
            }
            __syncthreads();
        }

        // epilogue: C(row,col) -> g_sim[(m*64+w)*25 + i*5 + j]
#pragma unroll
        for (int mt = 0; mt < 2; ++mt) {
#pragma unroll
            for (int nt = 0; nt < 4; ++nt) {
                int row0 = by*TBM + warpM*32 + mt*16 + grp;
                int col0 = bx*TBN + warpN*32 + nt*8 + 2*tig;
                float vals[4] = {acc[mt][nt].x, acc[mt][nt].y, acc[mt][nt].z, acc[mt][nt].w};
#pragma unroll
                for (int e = 0; e < 4; ++e) {
                    int row = row0 + (e >> 1)*8;
                    int col = col0 + (e & 1);
                    int m = row/5, ii = row%5, ww = col/5, jj = col%5;
                    g_sim[((size_t)(m*NW + ww))*25 + ii*5 + jj] = vals[e];
                }
            }
        }
    } else {
        // ---------- comb GEMM: per-p (2048x64) = qfA_p * pfB_p, 64-row tiles, FFMA2 ----------
        int tile = by & 31;       // 0..31 -> 64 rows each
        int p    = by >> 5;       // 0..4
        float* As = sm;           // [16][64]
        float* Bs = sm + 16*64;   // [16][64]

        const float* A = g_qfA + p*CCH;            const int lda = 5*CCH;
        const float* B = g_pfB + (size_t)p*CCH*NW; const int ldb = NW;

        int arow = tid >> 2;           // 0..31 (rows arow, arow+32)
        int acol = (tid & 3) * 4;
        int brow = tid >> 4;           // 0..7 (rows brow, brow+8)
        int bcol = (tid & 15) * 4;
        int ty = tid >> 4, tx = tid & 15;

        u64 acc[4][4];
#pragma unroll
        for (int i = 0; i < 4; ++i)
#pragma unroll
            for (int j = 0; j < 4; ++j) acc[i][j] = 0ull;

        const float* Ab = A + (size_t)(tile*64)*lda;

        for (int k0 = 0; k0 < CCH; k0 += 16) {
            float4 a0 = *(const float4*)(Ab + (size_t)arow*lda + k0 + acol);
            float4 a1 = *(const float4*)(Ab + (size_t)(arow+32)*lda + k0 + acol);
            float4 b0 = *(const float4*)(B  + (size_t)(k0+brow)*ldb + bcol);
            float4 b1 = *(const float4*)(B  + (size_t)(k0+brow+8)*ldb + bcol);
            __syncthreads();
            As[(acol+0)*64 + arow]    = a0.x; As[(acol+1)*64 + arow]    = a0.y;
            As[(acol+2)*64 + arow]    = a0.z; As[(acol+3)*64 + arow]    = a0.w;
            As[(acol+0)*64 + arow+32] = a1.x; As[(acol+1)*64 + arow+32] = a1.y;
            As[(acol+2)*64 + arow+32] = a1.z; As[(acol+3)*64 + arow+32] = a1.w;
            *(float4*)&Bs[brow*64 + bcol]     = b0;
            *(float4*)&Bs[(brow+8)*64 + bcol] = b1;
            __syncthreads();
#pragma unroll
            for (int k = 0; k < 16; ++k) {
                const u64* ap = (const u64*)&As[k*64 + ty*8];
                u64 a2[4] = {ap[0], ap[1], ap[2], ap[3]};
                float4 bv = *(const float4*)&Bs[k*64 + tx*4];
                u64 b2[4] = {pack2(bv.x,bv.x), pack2(bv.y,bv.y),
                             pack2(bv.z,bv.z), pack2(bv.w,bv.w)};
#pragma unroll
                for (int ip = 0; ip < 4; ++ip)
#pragma unroll
                    for (int j = 0; j < 4; ++j) ffma2(acc[ip][j], a2[ip], b2[j]);
            }
        }

        int row0 = tile*64 + ty*8;
        int col0 = tx*4;
#pragma unroll
        for (int ip = 0; ip < 4; ++ip)
#pragma unroll
            for (int j = 0; j < 4; ++j) {
                float lo, hi; unpack2(acc[ip][j], lo, hi);
                int r_lo = row0 + 2*ip, r_hi = r_lo + 1;
                int cc = col0 + j;
                g_comb[(size_t)r_lo*(NW*5) + cc*5 + p] = lo;
                g_comb[(size_t)r_hi*(NW*5) + cc*5 + p] = hi;
            }
    }
}

// ---------------- Kernel 3: Sinkhorn (scalar, rescaled) + early-exit (5-iter chunks) ----------------
__global__ void __launch_bounds__(128) sinkhorn_kernel(float* __restrict__ out) {
    int t = blockIdx.x*128 + threadIdx.x;

    float a[5]; float ws = 0.f;
#pragma unroll
    for (int p = 0; p < 5; ++p) {
        float wv = fmaxf(g_comb[(size_t)t*5 + p], 0.f) + 0.00101f;
        a[p] = wv; ws += wv;
    }
    float sc = __fdividef(5.f, ws);
#pragma unroll
    for (int p = 0; p < 5; ++p) a[p] *= sc;

    float K[25];
    const float* sp = g_sim + (size_t)t*25;
#pragma unroll
    for (int e = 0; e < 25; ++e) K[e] = __expf(20.f * sp[e]);

    float u[5], v[5];
#pragma unroll
    for (int j = 0; j < 5; ++j) v[j] = 1.f;

#pragma unroll 1
    for (int chunk = 0; chunk < 20; ++chunk) {
        float vs[5];
#pragma unroll
        for (int j = 0; j < 5; ++j) vs[j] = v[j];

#pragma unroll
        for (int s = 0; s < 5; ++s) {
#pragma unroll
            for (int i = 0; i < 5; ++i) {
                float acc = K[i*5+0]*v[0];
                acc = fmaf(K[i*5+1], v[1], acc);
                acc = fmaf(K[i*5+2], v[2], acc);
                acc = fmaf(K[i*5+3], v[3], acc);
                acc = fmaf(K[i*5+4], v[4], acc);
                u[i] = __fdividef(a[i], acc);
            }
#pragma unroll
            for (int j = 0; j < 5; ++j) {
                float acc = K[0*5+j]*u[0];
                acc = fmaf(K[1*5+j], u[1], acc);
                acc = fmaf(K[2*5+j], u[2], acc);
                acc = fmaf(K[3*5+j], u[3], acc);
                acc = fmaf(K[4*5+j], u[4], acc);
                v[j] = __fdividef(a[j], acc);
            }
        }

        bool conv = true;
#pragma unroll
        for (int j = 0; j < 5; ++j)
            conv = conv && (fabsf(v[j] - vs[j]) <= 1e-6f * v[j]);
        if (__all_sync(0xffffffffu, conv)) break;
    }

    float L = 0.f;
#pragma unroll
    for (int i = 0; i < 5; ++i) {
        float ui = u[i];
#pragma unroll
        for (int j = 0; j < 5; ++j)
            L = fmaf(sp[i*5+j] * ui, K[i*5+j]*v[j], L);
    }
    out[t] = L * 2.5f;
}

// ---------------- launch ----------------
extern "C" void kernel_launch(void* const* d_in, const int* in_sizes, int n_in,
                              void* d_out, int out_size) {
    const float* proto = (const float*)d_in[0];
    const float* query = (const float*)d_in[1];
    if (n_in >= 2 && in_sizes[0] > in_sizes[1]) {
        proto = (const float*)d_in[1];
        query = (const float*)d_in[0];
    }
    float* out = (float*)d_out;

    static bool attr_set = false;
    if (!attr_set) {
        cudaFuncSetAttribute(feat_kernel, cudaFuncAttributeMaxDynamicSharedMemorySize, 64000);
        cudaFuncSetAttribute(gemm_mega, cudaFuncAttributeMaxDynamicSharedMemorySize, SMEM_GEMM);
        attr_set = true;
    }

    feat_kernel<<<NQ + NW, 640, 64000>>>(proto, query);
    gemm_mega<<<dim3(6, 160), 128, SMEM_GEMM>>>();  // bx<5: sim (M=64); bx==5: comb (by=tile+32p)
    sinkhorn_kernel<<<(NQ*NW)/128, 128>>>(out);
}